// round 14
// baseline (speedup 1.0000x reference)
#include <cuda_runtime.h>
#include <math.h>
#include <stdint.h>

#define T_TOKENS 16384
#define HID      2048
#define NEXP     64
#define BT       128
#define KT       32
#define NST      (HID / KT)        // 64
#define NBLOCKS  (T_TOKENS / BT)   // 128

#define OFF_MULT  0
#define OFF_GATES (T_TOKENS * 2)
#define OFF_SEL   (OFF_GATES + T_TOKENS * NEXP)
#define OFF_Z     (OFF_SEL + T_TOKENS * 2)

// ---- smem layout (floats) ---- (identical to R13, proven correct)
#define A_CST   132
#define A_BUF   (32 * A_CST)        // 4224
#define B_RST   40
#define B_BUF   (32 * B_RST)        // 1280
#define BD_BUF  (32 * 64)           // 2048
#define APL_O   0
#define AH_O    (2 * A_BUF)         // 8448
#define AL_O    (4 * A_BUF)         // 16896
#define BH_O    (6 * A_BUF)         // 25344
#define BL_O    (BH_O + 2 * B_BUF)  // 27904
#define BD_O    (BL_O + 2 * B_BUF)  // 30464
#define DYN_FLOATS (BD_O + 2 * BD_BUF)  // 34560
#define DYN_BYTES  (DYN_FLOATS * 4)     // 138240
#define LS      68

#define ZSCALE 268435456.0

__device__ unsigned long long g_zacc;
__device__ unsigned int       g_zcnt;

__device__ __host__ __forceinline__ int CK(int kl) {
    return ((kl >> 3) << 3) + 2 * (kl & 3) + ((kl & 7) >> 2);
}

__device__ __forceinline__ float tf32_rna(float v) {
    uint32_t u; asm("cvt.rna.tf32.f32 %0, %1;" : "=r"(u) : "f"(v));
    return __uint_as_float(u);
}

__device__ __forceinline__ void mma_tf32(float* d,
                                         uint32_t a0, uint32_t a1, uint32_t a2, uint32_t a3,
                                         uint32_t b0, uint32_t b1) {
    asm volatile(
        "mma.sync.aligned.m16n8k8.row.col.f32.tf32.tf32.f32 "
        "{%0,%1,%2,%3}, {%4,%5,%6,%7}, {%8,%9}, {%0,%1,%2,%3};"
        : "+f"(d[0]), "+f"(d[1]), "+f"(d[2]), "+f"(d[3])
        : "r"(a0), "r"(a1), "r"(a2), "r"(a3), "r"(b0), "r"(b1));
}

__device__ __forceinline__ void ffma2(unsigned long long& d,
                                      unsigned long long a,
                                      unsigned long long b) {
    asm("fma.rn.f32x2 %0, %1, %2, %0;" : "+l"(d) : "l"(a), "l"(b));
}

extern __shared__ float sdyn[];

__global__ __launch_bounds__(256, 1)
void router_kernel(const float* __restrict__ x, const float* __restrict__ w,
                   float* __restrict__ out)
{
    __shared__ float Zs[BT];

    const int tid  = threadIdx.x;
    const int wid  = tid >> 5;
    const int lane = tid & 31;
    const int blk  = blockIdx.x;

    // ---------------- producer indexing (identical to R13) ----------------
    const int tr = tid >> 1;
    const int kh = (tid & 1) * 16;
    const int posA = (tr >> 4) * 16 + 2 * (tr & 7) + ((tr & 15) >> 3);
    int aoff[16];
#pragma unroll
    for (int t = 0; t < 16; t++)
        aoff[t] = (kh + CK(t)) * A_CST + posA;
    const float4* xA = (const float4*)(x + (size_t)(blk * BT + tr) * HID + kh);

    const int lp  = tid & 127;
    const int bn  = lp >> 2;
    const int kq  = lp & 3;
    int boff[8];
#pragma unroll
    for (int t = 0; t < 8; t++) {
        int kl = kq * 4 + (t >> 2) * 16 + (t & 3);
        boff[t] = bn * B_RST + CK(kl);
    }
    const int bexp = (tid < 128) ? bn : (32 + bn);
    const float4* wB = (const float4*)(w + (size_t)bexp * HID + kq * 4);

    // ---------------- consumer indexing (every warp does BOTH paths) ----------------
    // HMMA: warp tile 16 tokens x 32 experts (experts 0-31)
    const int wm = wid * 16;
    const int fr = lane >> 2;
    const int fc = lane & 3;
    // FFMA2: thread tile 4 tokens x 4 experts (experts 32-63)
    const int tx = tid & 7;
    const int ty = tid >> 3;

    float acc[4][4];                    // HMMA persistent fp32 accum (4 n-tiles)
    unsigned long long acc2[2][4];      // FFMA2 packed accum (2 token-pairs x 4 exp)
#pragma unroll
    for (int nt = 0; nt < 4; nt++)
#pragma unroll
        for (int q = 0; q < 4; q++) acc[nt][q] = 0.f;
#pragma unroll
    for (int p = 0; p < 2; p++)
#pragma unroll
        for (int e = 0; e < 4; e++) acc2[p][e] = 0ull;

    // ---------------- prologue: fill stage 0 (identical to R13) ----------------
    {
        float4 a4[4]; float4 b4[2];
#pragma unroll
        for (int j = 0; j < 4; j++) a4[j] = xA[j];
        b4[0] = wB[0]; b4[1] = wB[4];

        float* pAP = sdyn + APL_O;
        float* pAh = sdyn + AH_O;
        float* pAl = sdyn + AL_O;
        const float* av = (const float*)a4;
#pragma unroll
        for (int t = 0; t < 16; t++) {
            float v = av[t];
            pAP[(kh + t) * A_CST + tr] = v;
            float h = tf32_rna(v); float l = tf32_rna(v - h);
            pAh[aoff[t]] = h; pAl[aoff[t]] = l;
        }
        const float* bv = (const float*)b4;
        if (tid < 128) {
            float* pBh = sdyn + BH_O;
            float* pBl = sdyn + BL_O;
#pragma unroll
            for (int t = 0; t < 8; t++) {
                float v = bv[t]; float h = tf32_rna(v); float l = tf32_rna(v - h);
                pBh[boff[t]] = h; pBl[boff[t]] = l;
            }
        } else {
            float* pBD = sdyn + BD_O;
#pragma unroll
            for (int t = 0; t < 8; t++) {
                int kl = kq * 4 + (t >> 2) * 16 + (t & 3);
                float v = bv[t];
                *(float2*)&pBD[kl * 64 + bn * 2] = make_float2(v, v);
            }
        }
    }
    __syncthreads();

    // ---------------- main pipeline ----------------
#pragma unroll 1
    for (int s = 0; s < NST; s++) {
        const int buf = s & 1;
        const bool pf = (s + 1 < NST);

        float4 a4[4]; float4 b4[2];
        if (pf) {
            const int f4 = (s + 1) * (KT / 4);
#pragma unroll
            for (int j = 0; j < 4; j++) a4[j] = xA[f4 + j];
            b4[0] = wB[f4]; b4[1] = wB[f4 + 4];
        }

        // ---- fused consumer: HMMA (experts 0-31) interleaved with FFMA2 (32-63) ----
        {
            float tmp[4][4];
#pragma unroll
            for (int nt = 0; nt < 4; nt++)
#pragma unroll
                for (int q = 0; q < 4; q++) tmp[nt][q] = 0.f;

            const float* pAh = sdyn + AH_O + buf * A_BUF;
            const float* pAl = sdyn + AL_O + buf * A_BUF;
            const float* pBh = sdyn + BH_O + buf * B_BUF;
            const float* pBl = sdyn + BL_O + buf * B_BUF;
            const float* pAP = sdyn + APL_O + buf * A_BUF;
            const float* pBD = sdyn + BD_O + buf * BD_BUF;

#pragma unroll
            for (int kc = 0; kc < 4; kc++) {
                // HMMA fragments for this k8
                const int ca = (kc * 8 + 2 * fc) * A_CST + wm + 2 * fr;
                uint2 ah0 = *(const uint2*)&pAh[ca];
                uint2 ah1 = *(const uint2*)&pAh[ca + A_CST];
                uint2 al0 = *(const uint2*)&pAl[ca];
                uint2 al1 = *(const uint2*)&pAl[ca + A_CST];
                uint2 bh[4], bl[4];
#pragma unroll
                for (int nt = 0; nt < 4; nt++) {
                    const int bo = (nt * 8 + fr) * B_RST + kc * 8 + 2 * fc;
                    bh[nt] = *(const uint2*)&pBh[bo];
                    bl[nt] = *(const uint2*)&pBl[bo];
                }
#pragma unroll
                for (int nt = 0; nt < 4; nt++)
                    mma_tf32(tmp[nt], ah0.x, ah0.y, ah1.x, ah1.y, bh[nt].x, bh[nt].y);
#pragma unroll
                for (int nt = 0; nt < 4; nt++)
                    mma_tf32(tmp[nt], ah0.x, ah0.y, ah1.x, ah1.y, bl[nt].x, bl[nt].y);
#pragma unroll
                for (int nt = 0; nt < 4; nt++)
                    mma_tf32(tmp[nt], al0.x, al0.y, al1.x, al1.y, bh[nt].x, bh[nt].y);

                // FFMA2 over the same 8 k's (independent of HMMA results)
#pragma unroll
                for (int kk = 0; kk < 8; kk++) {
                    const int k = kc * 8 + kk;
                    ulonglong2 ap = *(const ulonglong2*)&pAP[k * A_CST + ty * 4];
                    ulonglong2 b01 = *(const ulonglong2*)&pBD[k * 64 + tx * 8];
                    ulonglong2 b23 = *(const ulonglong2*)&pBD[k * 64 + tx * 8 + 4];
                    ffma2(acc2[0][0], ap.x, b01.x); ffma2(acc2[0][1], ap.x, b01.y);
                    ffma2(acc2[0][2], ap.x, b23.x); ffma2(acc2[0][3], ap.x, b23.y);
                    ffma2(acc2[1][0], ap.y, b01.x); ffma2(acc2[1][1], ap.y, b01.y);
                    ffma2(acc2[1][2], ap.y, b23.x); ffma2(acc2[1][3], ap.y, b23.y);
                }
            }

            // fold HMMA stage partial into persistent fp32 accumulators
#pragma unroll
            for (int nt = 0; nt < 4; nt++)
#pragma unroll
                for (int q = 0; q < 4; q++) acc[nt][q] += tmp[nt][q];
        }
        __syncthreads();

        if (pf) {
            const int nbuf = (s + 1) & 1;
            float* pAP = sdyn + APL_O + nbuf * A_BUF;
            float* pAh = sdyn + AH_O + nbuf * A_BUF;
            float* pAl = sdyn + AL_O + nbuf * A_BUF;
            const float* av = (const float*)a4;
#pragma unroll
            for (int t = 0; t < 16; t++) {
                float v = av[t];
                pAP[(kh + t) * A_CST + tr] = v;
                float h = tf32_rna(v); float l = tf32_rna(v - h);
                pAh[aoff[t]] = h; pAl[aoff[t]] = l;
            }
            const float* bv = (const float*)b4;
            if (tid < 128) {
                float* pBh = sdyn + BH_O + nbuf * B_BUF;
                float* pBl = sdyn + BL_O + nbuf * B_BUF;
#pragma unroll
                for (int t = 0; t < 8; t++) {
                    float v = bv[t]; float h = tf32_rna(v); float l = tf32_rna(v - h);
                    pBh[boff[t]] = h; pBl[boff[t]] = l;
                }
            } else {
                float* pBD = sdyn + BD_O + nbuf * BD_BUF;
#pragma unroll
                for (int t = 0; t < 8; t++) {
                    int kl = kq * 4 + (t >> 2) * 16 + (t & 3);
                    float v = bv[t];
                    *(float2*)&pBD[kl * 64 + bn * 2] = make_float2(v, v);
                }
            }
            __syncthreads();
        }
    }

    // ---------------- accumulators -> logits smem ----------------
    float* lg = sdyn;
    {
        // HMMA half: experts 0-31
#pragma unroll
        for (int nt = 0; nt < 4; nt++) {
            const int t0 = wm + fr;
            const int c  = nt * 8 + fc * 2;
            float2 lo2, hi2;
            lo2.x = acc[nt][0]; lo2.y = acc[nt][1];
            hi2.x = acc[nt][2]; hi2.y = acc[nt][3];
            *(float2*)&lg[t0 * LS + c]       = lo2;
            *(float2*)&lg[(t0 + 8) * LS + c] = hi2;
        }
    }
    __syncthreads();   // HMMA writes done before FFMA2 writes to same rows (different cols; sync for safety ordering with reads below anyway)
    {
        // FFMA2 half: experts 32-63
#pragma unroll
        for (int p = 0; p < 2; p++)
#pragma unroll
            for (int e = 0; e < 4; e++) {
                unsigned long long v = acc2[p][e];
                const int c = 32 + tx * 4 + e;
                lg[(ty * 4 + 2 * p)     * LS + c] = __uint_as_float((unsigned)v);
                lg[(ty * 4 + 2 * p + 1) * LS + c] = __uint_as_float((unsigned)(v >> 32));
            }
    }
    __syncthreads();

    // ---------------- routing: thread t owns token t ----------------
    if (tid < BT) {
        const int tg = blk * BT + tid;
        const float NEG_INF = __int_as_float(0xff800000);

        float l[64];
#pragma unroll
        for (int c = 0; c < 64; c += 4) {
            float4 v = *(const float4*)&lg[tid * LS + c];
            l[c] = v.x; l[c + 1] = v.y; l[c + 2] = v.z; l[c + 3] = v.w;
        }

        float mx = l[0]; int ax = 0;
#pragma unroll
        for (int i = 1; i < 64; i++)
            if (l[i] > mx) { mx = l[i]; ax = i; }

        float so = 0.f, s1 = 0.f;
#pragma unroll
        for (int i = 0; i < 64; i++) {
            float e = expf(l[i] - mx);
            so += e;
            float f = fmaxf(fabsf(l[i]), mx);
            if (!((mx - l[i]) / f > 0.02f)) s1 += e;   // NaN-exact mask semantics
        }

        float mx2 = NEG_INF; int ax2 = 0;
#pragma unroll
        for (int i = 0; i < 64; i++) {
            float v = (i == ax) ? NEG_INF : l[i];
            if (v > mx2) { mx2 = v; ax2 = i; }
        }
        float s2 = 0.f;
#pragma unroll
        for (int i = 0; i < 64; i++) {
            if (i != ax) {
                float f = fmaxf(fabsf(l[i]), mx2);
                if (!((mx2 - l[i]) / f > 0.02f)) s2 += expf(l[i] - mx2);
            }
        }

        const float inv = 1.f / so;
        float* gout = out + OFF_GATES + (size_t)tg * NEXP;
#pragma unroll
        for (int c = 0; c < 64; c += 4) {
            float4 g;
            g.x = expf(l[c + 0] - mx) * inv;
            g.y = expf(l[c + 1] - mx) * inv;
            g.z = expf(l[c + 2] - mx) * inv;
            g.w = expf(l[c + 3] - mx) * inv;
            *(float4*)(gout + c) = g;
        }
        out[OFF_MULT + tg * 2 + 0] = 1.f / s1;
        out[OFF_MULT + tg * 2 + 1] = 1.f / s2;
        out[OFF_SEL  + tg * 2 + 0] = (float)ax;
        out[OFF_SEL  + tg * 2 + 1] = (float)ax2;
        float lse = mx + logf(so);
        Zs[tid] = lse * lse;
    }
    __syncthreads();

    // ---------------- fused z-loss (deterministic fixed-point, proven R13) ----------------
    if (tid < 32) {
        float v = ((Zs[tid] + Zs[tid + 32]) + Zs[tid + 64]) + Zs[tid + 96];
#pragma unroll
        for (int mm = 16; mm; mm >>= 1) v += __shfl_xor_sync(0xffffffffu, v, mm, 32);
        if (tid == 0) {
            unsigned long long inc = (unsigned long long)((double)v * ZSCALE + 0.5);
            atomicAdd(&g_zacc, inc);
            __threadfence();
            unsigned old = atomicAdd(&g_zcnt, 1u);
            if (old == NBLOCKS - 1) {
                unsigned long long tot = atomicExch(&g_zacc, 0ull);
                atomicExch(&g_zcnt, 0u);
                out[OFF_Z] = (float)(0.001 * ((double)tot / ZSCALE) / (double)T_TOKENS);
            }
        }
    }
}

extern "C" void kernel_launch(void* const* d_in, const int* in_sizes, int n_in,
                              void* d_out, int out_size)
{
    const float* x = (const float*)d_in[0];
    const float* w = (const float*)d_in[1];
    float* out = (float*)d_out;
    cudaFuncSetAttribute(router_kernel, cudaFuncAttributeMaxDynamicSharedMemorySize, DYN_BYTES);
    router_kernel<<<NBLOCKS, 256, DYN_BYTES>>>(x, w, out);
}

// round 16
// speedup vs baseline: 2.4038x; 2.4038x over previous
#include <cuda_runtime.h>
#include <cuda_fp16.h>
#include <math.h>
#include <stdint.h>
#include <string.h>

#define T_TOKENS 16384
#define HID      2048
#define NEXP     64
#define BT       128
#define KT       32
#define NST      (HID / KT)        // 64
#define NBLOCKS  (T_TOKENS / BT)   // 128

#define OFF_MULT  0
#define OFF_GATES (T_TOKENS * 2)
#define OFF_SEL   (OFF_GATES + T_TOKENS * NEXP)
#define OFF_Z     (OFF_SEL + T_TOKENS * 2)

// ---- smem word (uint32 = half2 pair) layout ----
#define ATS     136                 // A row stride in words (136 % 32 == 8)
#define A_BUFW  (16 * ATS)          // 2176 words per A matrix per buffer
#define BTS     72                  // B row stride in words (72 % 32 == 8)
#define B_BUFW  (16 * BTS)          // 1152 words
#define AH_O    0
#define AL_O    (2 * A_BUFW)        // 4352
#define BH_O    (4 * A_BUFW)        // 8704
#define BL_O    (BH_O + 2 * B_BUFW) // 11008
#define DYN_WORDS (BL_O + 2 * B_BUFW)   // 13312
#define DYN_BYTES (DYN_WORDS * 4)       // 53248
#define LS      68                  // logits row stride (floats), aliases A region

#define LO_SCALE   2048.0f
#define LO_UNSCALE 4.8828125e-4f    // 2^-11 exact

#define ZSCALE 268435456.0

__device__ unsigned long long g_zacc;
__device__ unsigned int       g_zcnt;

__device__ __forceinline__ uint32_t h2u(__half2 h) {
    uint32_t u; memcpy(&u, &h, 4); return u;
}

__device__ __forceinline__ void mma16(float* d, const uint32_t* a, const uint32_t* b) {
    asm volatile(
        "mma.sync.aligned.m16n8k16.row.col.f32.f16.f16.f32 "
        "{%0,%1,%2,%3}, {%4,%5,%6,%7}, {%8,%9}, {%0,%1,%2,%3};"
        : "+f"(d[0]), "+f"(d[1]), "+f"(d[2]), "+f"(d[3])
        : "r"(a[0]), "r"(a[1]), "r"(a[2]), "r"(a[3]), "r"(b[0]), "r"(b[1]));
}

extern __shared__ uint32_t sw[];

__global__ __launch_bounds__(256, 1)
void router_kernel(const float* __restrict__ x, const float* __restrict__ w,
                   float* __restrict__ out)
{
    __shared__ float Zs[BT];

    const int tid  = threadIdx.x;
    const int wid  = tid >> 5;
    const int lane = tid & 31;
    const int blk  = blockIdx.x;

    // ---------------- producer indexing ----------------
    // A: thread -> token tr, k-half kh (16 fp32 per stage)
    const int tr = tid >> 1;
    const int kh = (tid & 1) * 16;
    const float4* xA = (const float4*)(x + (size_t)(blk * BT + tr) * HID + kh);
    // B: thread -> expert n, pair-phase kq (pairs kp = kq + 4j)
    const int bn = tid >> 2;
    const int kq = tid & 3;
    const float* wB = w + (size_t)bn * HID + 2 * kq;

    // ---------------- consumer indexing ----------------
    const int wm = (wid & 3) * 32;   // token tile base
    const int wn = (wid >> 2) * 32;  // expert tile base
    const int fr = lane >> 2;
    const int fc = lane & 3;

    float acc[2][4][4];      // persistent fp32
    float hh[2][4][4], hl[2][4][4], lh[2][4][4];   // term accumulators (chains)
#pragma unroll
    for (int mt = 0; mt < 2; mt++)
#pragma unroll
        for (int nt = 0; nt < 4; nt++)
#pragma unroll
            for (int q = 0; q < 4; q++) {
                acc[mt][nt][q] = 0.f;
                hh[mt][nt][q] = 0.f; hl[mt][nt][q] = 0.f; lh[mt][nt][q] = 0.f;
            }

    // ---------------- producer store helper (macro to keep regs tight) ----------------
#define PRODUCE(bufidx, a4, b2)                                                   \
    {                                                                             \
        uint32_t* pAH = sw + AH_O + (bufidx) * A_BUFW;                            \
        uint32_t* pAL = sw + AL_O + (bufidx) * A_BUFW;                            \
        const float* av = (const float*)(a4);                                     \
        _Pragma("unroll")                                                         \
        for (int j = 0; j < 8; j++) {                                             \
            float v0 = av[2 * j], v1 = av[2 * j + 1];                             \
            __half2 h2 = __floats2half2_rn(v0, v1);                               \
            float h0 = __low2float(h2), h1 = __high2float(h2);                    \
            __half2 l2 = __floats2half2_rn((v0 - h0) * LO_SCALE,                  \
                                           (v1 - h1) * LO_SCALE);                 \
            int kp = (kh >> 1) + j;                                               \
            pAH[kp * ATS + tr] = h2u(h2);                                         \
            pAL[kp * ATS + tr] = h2u(l2);                                         \
        }                                                                         \
        uint32_t* pBH = sw + BH_O + (bufidx) * B_BUFW;                            \
        uint32_t* pBL = sw + BL_O + (bufidx) * B_BUFW;                            \
        const float* bv = (const float*)(b2);                                     \
        _Pragma("unroll")                                                         \
        for (int j = 0; j < 4; j++) {                                             \
            float v0 = bv[2 * j], v1 = bv[2 * j + 1];                             \
            __half2 h2 = __floats2half2_rn(v0, v1);                               \
            float h0 = __low2float(h2), h1 = __high2float(h2);                    \
            __half2 l2 = __floats2half2_rn((v0 - h0) * LO_SCALE,                  \
                                           (v1 - h1) * LO_SCALE);                 \
            int kp = kq + 4 * j;                                                  \
            pBH[kp * BTS + bn] = h2u(h2);                                         \
            pBL[kp * BTS + bn] = h2u(l2);                                         \
        }                                                                         \
    }

    // ---------------- prologue: fill stage 0 ----------------
    {
        float4 a4[4];
#pragma unroll
        for (int j = 0; j < 4; j++) a4[j] = xA[j];
        float2 b2[4];
#pragma unroll
        for (int j = 0; j < 4; j++) b2[j] = *(const float2*)(wB + 8 * j);
        PRODUCE(0, a4, b2);
    }
    __syncthreads();

    // ---------------- main pipeline ----------------
#pragma unroll 1
    for (int s = 0; s < NST; s++) {
        const int buf = s & 1;
        const bool pf = (s + 1 < NST);

        float4 a4[4]; float2 b2[4];
        if (pf) {
            const int f4 = (s + 1) * 8;
#pragma unroll
            for (int j = 0; j < 4; j++) a4[j] = xA[f4 + j];
#pragma unroll
            for (int j = 0; j < 4; j++) b2[j] = *(const float2*)(wB + (s + 1) * 32 + 8 * j);
        }

        // ---- consume current buffer ----
        {
            const uint32_t* pAH = sw + AH_O + buf * A_BUFW;
            const uint32_t* pAL = sw + AL_O + buf * A_BUFW;
            const uint32_t* pBH = sw + BH_O + buf * B_BUFW;
            const uint32_t* pBL = sw + BL_O + buf * B_BUFW;
#pragma unroll
            for (int kc = 0; kc < 2; kc++) {
                const int kb = kc * 8;
                uint32_t ah[2][4], al[2][4];
#pragma unroll
                for (int mt = 0; mt < 2; mt++) {
                    const int rm = wm + mt * 16 + fr;
                    ah[mt][0] = pAH[(kb + fc) * ATS + rm];
                    ah[mt][1] = pAH[(kb + fc) * ATS + rm + 8];
                    ah[mt][2] = pAH[(kb + fc + 4) * ATS + rm];
                    ah[mt][3] = pAH[(kb + fc + 4) * ATS + rm + 8];
                    al[mt][0] = pAL[(kb + fc) * ATS + rm];
                    al[mt][1] = pAL[(kb + fc) * ATS + rm + 8];
                    al[mt][2] = pAL[(kb + fc + 4) * ATS + rm];
                    al[mt][3] = pAL[(kb + fc + 4) * ATS + rm + 8];
                }
                uint32_t bh[4][2], bl[4][2];
#pragma unroll
                for (int nt = 0; nt < 4; nt++) {
                    const int cn = wn + nt * 8 + fr;
                    bh[nt][0] = pBH[(kb + fc) * BTS + cn];
                    bh[nt][1] = pBH[(kb + fc + 4) * BTS + cn];
                    bl[nt][0] = pBL[(kb + fc) * BTS + cn];
                    bl[nt][1] = pBL[(kb + fc + 4) * BTS + cn];
                }
#pragma unroll
                for (int mt = 0; mt < 2; mt++)
#pragma unroll
                    for (int nt = 0; nt < 4; nt++)
                        mma16(hh[mt][nt], ah[mt], bh[nt]);
#pragma unroll
                for (int mt = 0; mt < 2; mt++)
#pragma unroll
                    for (int nt = 0; nt < 4; nt++)
                        mma16(hl[mt][nt], ah[mt], bl[nt]);
#pragma unroll
                for (int mt = 0; mt < 2; mt++)
#pragma unroll
                    for (int nt = 0; nt < 4; nt++)
                        mma16(lh[mt][nt], al[mt], bh[nt]);
            }
        }

        // fold term chains into fp32 accumulators every 2 stages (chain len 4)
        if (buf == 1) {
#pragma unroll
            for (int mt = 0; mt < 2; mt++)
#pragma unroll
                for (int nt = 0; nt < 4; nt++)
#pragma unroll
                    for (int q = 0; q < 4; q++) {
                        acc[mt][nt][q] += fmaf(hl[mt][nt][q] + lh[mt][nt][q],
                                               LO_UNSCALE, hh[mt][nt][q]);
                        hh[mt][nt][q] = 0.f; hl[mt][nt][q] = 0.f; lh[mt][nt][q] = 0.f;
                    }
        }
        __syncthreads();

        if (pf) {
            PRODUCE(buf ^ 1, a4, b2);
            __syncthreads();
        }
    }

    // ---------------- acc -> logits smem ----------------
    float* lg = (float*)sw;   // 128 x 68 floats, aliases A region (8704 words)
#pragma unroll
    for (int mt = 0; mt < 2; mt++)
#pragma unroll
        for (int nt = 0; nt < 4; nt++) {
            const int t0 = wm + mt * 16 + fr;
            const int c  = wn + nt * 8 + fc * 2;
            float2 lo2, hi2;
            lo2.x = acc[mt][nt][0]; lo2.y = acc[mt][nt][1];
            hi2.x = acc[mt][nt][2]; hi2.y = acc[mt][nt][3];
            *(float2*)&lg[t0 * LS + c]       = lo2;
            *(float2*)&lg[(t0 + 8) * LS + c] = hi2;
        }
    __syncthreads();

    // ---------------- routing: thread t owns token t ----------------
    if (tid < BT) {
        const int tg = blk * BT + tid;
        const float NEG_INF = __int_as_float(0xff800000);

        float l[64];
#pragma unroll
        for (int c = 0; c < 64; c += 4) {
            float4 v = *(const float4*)&lg[tid * LS + c];
            l[c] = v.x; l[c + 1] = v.y; l[c + 2] = v.z; l[c + 3] = v.w;
        }

        float mx = l[0]; int ax = 0;
#pragma unroll
        for (int i = 1; i < 64; i++)
            if (l[i] > mx) { mx = l[i]; ax = i; }

        float so = 0.f, s1 = 0.f;
#pragma unroll
        for (int i = 0; i < 64; i++) {
            float e = expf(l[i] - mx);
            so += e;
            float f = fmaxf(fabsf(l[i]), mx);
            if (!((mx - l[i]) / f > 0.02f)) s1 += e;   // NaN-exact mask semantics
        }

        float mx2 = NEG_INF; int ax2 = 0;
#pragma unroll
        for (int i = 0; i < 64; i++) {
            float v = (i == ax) ? NEG_INF : l[i];
            if (v > mx2) { mx2 = v; ax2 = i; }
        }
        float s2 = 0.f;
#pragma unroll
        for (int i = 0; i < 64; i++) {
            if (i != ax) {
                float f = fmaxf(fabsf(l[i]), mx2);
                if (!((mx2 - l[i]) / f > 0.02f)) s2 += expf(l[i] - mx2);
            }
        }

        const float inv = 1.f / so;
        float* gout = out + OFF_GATES + (size_t)tg * NEXP;
#pragma unroll
        for (int c = 0; c < 64; c += 4) {
            float4 g;
            g.x = expf(l[c + 0] - mx) * inv;
            g.y = expf(l[c + 1] - mx) * inv;
            g.z = expf(l[c + 2] - mx) * inv;
            g.w = expf(l[c + 3] - mx) * inv;
            *(float4*)(gout + c) = g;
        }
        out[OFF_MULT + tg * 2 + 0] = 1.f / s1;
        out[OFF_MULT + tg * 2 + 1] = 1.f / s2;
        out[OFF_SEL  + tg * 2 + 0] = (float)ax;
        out[OFF_SEL  + tg * 2 + 1] = (float)ax2;
        float lse = mx + logf(so);
        Zs[tid] = lse * lse;
    }
    __syncthreads();

    // ---------------- fused z-loss (deterministic fixed-point, proven) ----------------
    if (tid < 32) {
        float v = ((Zs[tid] + Zs[tid + 32]) + Zs[tid + 64]) + Zs[tid + 96];
#pragma unroll
        for (int mm = 16; mm; mm >>= 1) v += __shfl_xor_sync(0xffffffffu, v, mm, 32);
        if (tid == 0) {
            unsigned long long inc = (unsigned long long)((double)v * ZSCALE + 0.5);
            atomicAdd(&g_zacc, inc);
            __threadfence();
            unsigned old = atomicAdd(&g_zcnt, 1u);
            if (old == NBLOCKS - 1) {
                unsigned long long tot = atomicExch(&g_zacc, 0ull);
                atomicExch(&g_zcnt, 0u);
                out[OFF_Z] = (float)(0.001 * ((double)tot / ZSCALE) / (double)T_TOKENS);
            }
        }
    }
}

extern "C" void kernel_launch(void* const* d_in, const int* in_sizes, int n_in,
                              void* d_out, int out_size)
{
    const float* x = (const float*)d_in[0];
    const float* w = (const float*)d_in[1];
    float* out = (float*)d_out;
    cudaFuncSetAttribute(router_kernel, cudaFuncAttributeMaxDynamicSharedMemorySize, DYN_BYTES);
    router_kernel<<<NBLOCKS, 256, DYN_BYTES>>>(x, w, out);
}